// round 6
// baseline (speedup 1.0000x reference)
#include <cuda_runtime.h>
#include <cstdint>

#define BATCH 32
#define NN 100
#define HH 32
#define DD 3200
#define NF 16
#define NSPLIT 50
#define ILEN (DD/NSPLIT)     // 64
#define CI 4
#define NCHUNK (ILEN/CI)     // 16
#define TO 128               // threads per gemm block; 1 output each
#define NW 1596              // unfold window count
#define GPARTS 5

// ---- scratch (device globals: allocation-free) ----
__device__ float g_hs[BATCH*DD];
__device__ float g_gpart[BATCH][GPARTS][3];
__device__ float g_feat[(size_t)DD*NF*BATCH];          // [i][f][b]  6.55 MB
__device__ float g_scratch[(size_t)NSPLIT*BATCH*DD];   // 20.48 MB

// ===================== stage 0: graph conv + layernorm -> hs (alpha fused) ==========
__global__ void k_gconv(const float* __restrict__ inputs,
                        const float* __restrict__ hidden,
                        const float* __restrict__ lap,
                        const float* __restrict__ corr,
                        const float* __restrict__ gc_w,
                        const float* __restrict__ gc_b,
                        const float* __restrict__ ln_g,
                        const float* __restrict__ ln_b) {
    int blk = blockIdx.x;            // b*100 + m
    int b = blk / NN;
    int m = blk % NN;
    int o = threadIdx.x;             // 0..31, one warp

    __shared__ float salpha[NN];
    for (int n = o; n < NN; n += 32) {
        float s = 0.f;
        #pragma unroll 4
        for (int bb = 0; bb < BATCH; ++bb) s += inputs[bb*NN + n];
        s *= (1.f/BATCH);
        salpha[n] = 1.f / (1.f + expf(-s));
    }
    __syncwarp();

    float axh = 0.f, ax0 = 0.f;
    for (int n = 0; n < NN; ++n) {
        float al = salpha[n];
        float a  = al * lap[m*NN + n] + (1.f - al) * corr[m*NN + n];
        ax0 += a * inputs[b*NN + n];
        axh += a * hidden[(size_t)(b*NN + n)*HH + o];
    }
    __shared__ float sax[HH];
    sax[o] = axh;
    __syncwarp();

    float h = gc_b[o] + ax0 * gc_w[o];       // f = 0 row (inputs channel)
    #pragma unroll
    for (int f = 0; f < HH; ++f)
        h += sax[f] * gc_w[(f+1)*HH + o];

    // layernorm over hidden dim (warp of 32)
    float mu = h;
    #pragma unroll
    for (int off = 16; off; off >>= 1) mu += __shfl_xor_sync(0xffffffffu, mu, off);
    mu *= (1.f/HH);
    float dv = h - mu;
    float v = dv*dv;
    #pragma unroll
    for (int off = 16; off; off >>= 1) v += __shfl_xor_sync(0xffffffffu, v, off);
    v *= (1.f/HH);
    float out = dv * rsqrtf(v + 1e-5f) * ln_g[o] + ln_b[o];
    g_hs[(size_t)blk*HH + o] = out;          // == b*3200 + m*32 + o
}

// ===================== stage 1: gating partials (full-chip) =====================
__global__ void k_gates_part() {
    int part = blockIdx.x;           // 0..GPARTS-1
    int b    = blockIdx.y;           // batch
    int tid  = threadIdx.x;          // 256 threads
    __shared__ float sh[DD];
    __shared__ float ct[10], st[10];
    __shared__ float red[3][256];

    if (tid < 10) { ct[tid] = cospif(0.2f * tid); st[tid] = sinpif(0.2f * tid); }
    for (int i = tid; i < DD; i += 256) sh[i] = g_hs[(size_t)b*DD + i];
    __syncthreads();

    float ps = 0.f, ss = 0.f, ns = 0.f;
    for (int w = part + GPARTS*tid; w < NW; w += GPARTS*256) {
        int s0 = 2*w;
        float x[10];
        #pragma unroll
        for (int j = 0; j < 10; ++j) x[j] = sh[s0 + j];
        #pragma unroll
        for (int k = 0; k < 10; ++k) {
            float re = 0.f, im = 0.f;
            #pragma unroll
            for (int j = 0; j < 10; ++j) {
                int t = (j*k) % 10;
                re += x[j] * ct[t];
                im += x[j] * st[t];
            }
            ps += sqrtf(re*re + im*im);
        }
        #pragma unroll
        for (int j = 0; j < 9; ++j) ss += fabsf(x[j+1] - x[j]);
    }
    for (int i = part + GPARTS*tid; i < DD-2; i += GPARTS*256)
        ns += fabsf(sh[i+2] - 2.f*sh[i+1] + sh[i]);

    red[0][tid] = ps; red[1][tid] = ss; red[2][tid] = ns;
    __syncthreads();
    for (int off = 128; off; off >>= 1) {
        if (tid < off) {
            red[0][tid] += red[0][tid+off];
            red[1][tid] += red[1][tid+off];
            red[2][tid] += red[2][tid+off];
        }
        __syncthreads();
    }
    if (tid == 0) {
        g_gpart[b][part][0] = red[0][0];
        g_gpart[b][part][1] = red[1][0];
        g_gpart[b][part][2] = red[2][0];
    }
}

// ===================== stage 2: gates finalize (per-block) + feature tensor ========
__global__ void k_featgates(const float* __restrict__ mnp, const float* __restrict__ mxp,
                            const float* __restrict__ mns, const float* __restrict__ mxs,
                            const float* __restrict__ mnn, const float* __restrict__ mxn) {
    __shared__ float sg[BATCH][3];
    int tid = threadIdx.x;
    if (tid < BATCH) {
        int b = tid;
        float psum = 0.f, ssum = 0.f, nsum = 0.f;
        #pragma unroll
        for (int k = 0; k < GPARTS; ++k) {
            psum += g_gpart[b][k][0];
            ssum += g_gpart[b][k][1];
            nsum += g_gpart[b][k][2];
        }
        float pstat = psum / (float)(NW*10);
        float sstat = ssum / (float)(NW*9);
        float nstat = nsum / (float)(DD-2);
        float p  = fabsf((pstat - *mnp) / (*mxp - *mnp + 1e-8f));
        float s  = 1.f - fabsf((sstat - *mns) / (*mxs - *mns + 1e-8f));
        float nv = fabsf((nstat - *mnn) / (*mxn - *mnn + 1e-8f));
        float a0 = fabsf(p), a1 = fabsf(s), a2 = fabsf(nv);
        float mm = fmaxf(a0, fmaxf(a1, a2));
        float e0 = expf(a0-mm), e1 = expf(a1-mm), e2 = expf(a2-mm);
        float inv = 1.f / (e0 + e1 + e2);
        sg[b][0] = e0*inv; sg[b][1] = e1*inv; sg[b][2] = e2*inv;
    }
    __syncthreads();

    int idx = blockIdx.x*blockDim.x + tid;
    if (idx >= BATCH*DD) return;
    int b = idx & 31;
    int i = idx >> 5;
    float x  = g_hs[(size_t)b*DD + i];
    float g0 = sg[b][0], g1 = sg[b][1], g2 = sg[b][2];
    float* fo = g_feat + (size_t)i*(NF*BATCH) + b;

    // Chebyshev: cos(d*arccos(tanh(xc))) == T_d(tanh(xc)) exactly
    float t  = tanhf(g0*x);
    float t2 = 2.f*t*t - 1.f;
    float t3 = 2.f*t*t2 - t;
    fo[0*BATCH] = 1.f; fo[1*BATCH] = t; fo[2*BATCH] = t2; fo[3*BATCH] = t3;

    // SiLU + B-spline bases (Cox-de Boor, uniform grid, K=3, GRID=5)
    float xb = g1*x;
    fo[4*BATCH] = xb / (1.f + expf(-xb));
    float bb[11];
    #pragma unroll
    for (int tt = 0; tt < 11; ++tt) {
        float gl = (float)(tt-3) * 0.4f - 1.f;
        float gr = (float)(tt-2) * 0.4f - 1.f;
        bb[tt] = (xb >= gl && xb < gr) ? 1.f : 0.f;
    }
    #pragma unroll
    for (int d = 1; d <= 3; ++d) {
        float inv = 1.f / (0.4f * (float)d);
        #pragma unroll
        for (int tt = 0; tt < 10; ++tt) {
            if (tt < 11 - d) {
                float gl = (float)(tt-3) * 0.4f - 1.f;          // grid[tt]
                float gr = (float)(tt+d+1-3) * 0.4f - 1.f;      // grid[tt+d+1]
                bb[tt] = (xb - gl)*inv*bb[tt] + (gr - xb)*inv*bb[tt+1];
            }
        }
    }
    #pragma unroll
    for (int k = 0; k < 8; ++k) fo[(5+k)*BATCH] = bb[k];

    // Taylor powers
    float xt = g2*x;
    fo[13*BATCH] = xt;
    fo[14*BATCH] = xt*xt;
    fo[15*BATCH] = xt*xt*xt;
}

// ===================== stage 3: fused 16-feature contraction (1 output/thread) =====
__device__ __forceinline__ void cpa16(void* s, const void* g) {
    unsigned ss = (unsigned)__cvta_generic_to_shared(s);
    asm volatile("cp.async.cg.shared.global [%0], [%1], 16;" :: "r"(ss), "l"(g));
}

__device__ __forceinline__ void loadW16(float* wv, int i, int o, float bwv,
                                        const float* __restrict__ cheb,
                                        const float* __restrict__ spline,
                                        const float* __restrict__ taylor) {
    float4 cw = *(const float4*)(cheb + (size_t)i*(DD*4) + (size_t)o*4);
    wv[0]=cw.x; wv[1]=cw.y; wv[2]=cw.z; wv[3]=cw.w;
    wv[4]=bwv;
    const float4* sp = (const float4*)(spline + (size_t)o*(DD*8) + (size_t)i*8);
    float4 s0 = sp[0], s1 = sp[1];
    wv[5]=s0.x; wv[6]=s0.y; wv[7]=s0.z; wv[8]=s0.w;
    wv[9]=s1.x; wv[10]=s1.y; wv[11]=s1.z; wv[12]=s1.w;
    const float* tp = taylor + (size_t)i*(DD*3) + (size_t)o*3;
    wv[13]=__ldg(tp+0); wv[14]=__ldg(tp+1); wv[15]=__ldg(tp+2);
}

__global__ void __launch_bounds__(TO, 6) k_gemm(const float* __restrict__ cheb,
                                                const float* __restrict__ basew,
                                                const float* __restrict__ spline,
                                                const float* __restrict__ taylor) {
    int o  = blockIdx.x*TO + threadIdx.x;   // blockIdx.x in [0,25)
    int sp = blockIdx.y;
    int i0 = sp * ILEN;

    __shared__ __align__(16) float sf[2][CI*NF*BATCH];  // 2 x 8 KB
    unsigned long long acc[16];                          // packed f32x2 per batch pair
    #pragma unroll
    for (int p = 0; p < 16; ++p) acc[p] = 0ull;

    // prologue: stage chunk 0 (128 threads x 4 float4 = 512 float4 = 8 KB)
    {
        const float4* src = (const float4*)(g_feat + (size_t)i0*(NF*BATCH));
        #pragma unroll
        for (int r = 0; r < 4; ++r)
            cpa16(&((float4*)sf[0])[threadIdx.x + r*TO], &src[threadIdx.x + r*TO]);
        asm volatile("cp.async.commit_group;");
    }

    for (int c = 0; c < NCHUNK; ++c) {
        if (c + 1 < NCHUNK) {
            const float4* src = (const float4*)(g_feat + (size_t)(i0 + (c+1)*CI)*(NF*BATCH));
            float4* dst = (float4*)sf[(c+1)&1];
            #pragma unroll
            for (int r = 0; r < 4; ++r)
                cpa16(&dst[threadIdx.x + r*TO], &src[threadIdx.x + r*TO]);
            asm volatile("cp.async.commit_group;");
            asm volatile("cp.async.wait_group 1;");
        } else {
            asm volatile("cp.async.wait_group 0;");
        }
        __syncthreads();

        const float* sb = sf[c&1];
        int ibase = i0 + c*CI;

        // basew for this chunk (contiguous in i): 1 float4
        float bw[4];
        {
            float4 a = *(const float4*)(basew + (size_t)o*DD + ibase);
            bw[0]=a.x; bw[1]=a.y; bw[2]=a.z; bw[3]=a.w;
        }

        #pragma unroll
        for (int ii = 0; ii < CI; ++ii) {
            int i = ibase + ii;
            float wv[16];
            loadW16(wv, i, o, bw[ii], cheb, spline, taylor);

            #pragma unroll
            for (int f = 0; f < 16; ++f) {
                unsigned int b0 = __float_as_uint(wv[f]);
                unsigned long long wA = ((unsigned long long)b0 << 32) | (unsigned long long)b0;
                const ulonglong2* fp = (const ulonglong2*)&sb[ii*(NF*BATCH) + f*BATCH];
                #pragma unroll
                for (int p = 0; p < 8; ++p) {
                    ulonglong2 q = fp[p];   // one LDS.128 feeds 2 FFMA2
                    asm("fma.rn.f32x2 %0, %1, %2, %0;" : "+l"(acc[2*p])   : "l"(q.x), "l"(wA));
                    asm("fma.rn.f32x2 %0, %1, %2, %0;" : "+l"(acc[2*p+1]) : "l"(q.y), "l"(wA));
                }
            }
        }
        __syncthreads();
    }

    #pragma unroll
    for (int p = 0; p < 16; ++p) {
        float2 v = *(float2*)&acc[p];
        g_scratch[((size_t)sp*BATCH + (2*p  ))*DD + o] = v.x;
        g_scratch[((size_t)sp*BATCH + (2*p+1))*DD + o] = v.y;
    }
}

// ===================== stage 4: split reduction -> d_out =====================
__global__ void k_reduce(float* __restrict__ out) {
    int j = blockIdx.x*blockDim.x + threadIdx.x;
    if (j < BATCH*DD) {
        float s = 0.f;
        #pragma unroll
        for (int k = 0; k < NSPLIT; ++k)
            s += g_scratch[(size_t)k*(BATCH*DD) + j];
        out[j] = s;
    }
}

extern "C" void kernel_launch(void* const* d_in, const int* in_sizes, int n_in,
                              void* d_out, int out_size) {
    const float* inputs = (const float*)d_in[0];
    const float* hidden = (const float*)d_in[1];
    const float* lap    = (const float*)d_in[2];
    const float* corr   = (const float*)d_in[3];
    const float* gc_w   = (const float*)d_in[4];
    const float* gc_b   = (const float*)d_in[5];
    const float* ln_g   = (const float*)d_in[6];
    const float* ln_b   = (const float*)d_in[7];
    const float* cheb   = (const float*)d_in[8];
    const float* basew  = (const float*)d_in[9];
    const float* spline = (const float*)d_in[10];
    const float* taylor = (const float*)d_in[11];

    k_gconv<<<BATCH*NN, 32>>>(inputs, hidden, lap, corr, gc_w, gc_b, ln_g, ln_b);
    k_gates_part<<<dim3(GPARTS, BATCH), 256>>>();
    k_featgates<<<(BATCH*DD + 255)/256, 256>>>((const float*)d_in[12], (const float*)d_in[13],
                                               (const float*)d_in[14], (const float*)d_in[15],
                                               (const float*)d_in[16], (const float*)d_in[17]);
    k_gemm<<<dim3(DD/TO, NSPLIT), TO>>>(cheb, basew, spline, taylor);
    k_reduce<<<(BATCH*DD + 255)/256, 256>>>((float*)d_out);
}

// round 7
// speedup vs baseline: 1.2552x; 1.2552x over previous
#include <cuda_runtime.h>
#include <cstdint>

#define BATCH 32
#define NN 100
#define HH 32
#define DD 3200
#define NF 16
#define NSPLIT 100
#define ILEN (DD/NSPLIT)     // 32
#define CI 4
#define NCHUNK (ILEN/CI)     // 8
#define TO 64                // threads per gemm block; 2 outputs each
#define NW 1596              // unfold window count
#define GPARTS 5

// ---- scratch (device globals: allocation-free) ----
__device__ float g_hs[BATCH*DD];
__device__ float g_gpart[BATCH][GPARTS][3];
__device__ float g_feat[(size_t)DD*NF*BATCH];          // [i][f][b]  6.55 MB
__device__ float g_scratch[(size_t)NSPLIT*BATCH*DD];   // 41 MB

// ===================== stage 0: graph conv + layernorm -> hs (alpha fused) ==========
__global__ void k_gconv(const float* __restrict__ inputs,
                        const float* __restrict__ hidden,
                        const float* __restrict__ lap,
                        const float* __restrict__ corr,
                        const float* __restrict__ gc_w,
                        const float* __restrict__ gc_b,
                        const float* __restrict__ ln_g,
                        const float* __restrict__ ln_b) {
    int blk = blockIdx.x;            // b*100 + m
    int b = blk / NN;
    int m = blk % NN;
    int o = threadIdx.x;             // 0..31, one warp

    __shared__ float salpha[NN];
    for (int n = o; n < NN; n += 32) {
        float s = 0.f;
        #pragma unroll 4
        for (int bb = 0; bb < BATCH; ++bb) s += inputs[bb*NN + n];
        s *= (1.f/BATCH);
        salpha[n] = 1.f / (1.f + expf(-s));
    }
    __syncwarp();

    float axh = 0.f, ax0 = 0.f;
    for (int n = 0; n < NN; ++n) {
        float al = salpha[n];
        float a  = al * lap[m*NN + n] + (1.f - al) * corr[m*NN + n];
        ax0 += a * inputs[b*NN + n];
        axh += a * hidden[(size_t)(b*NN + n)*HH + o];
    }
    __shared__ float sax[HH];
    sax[o] = axh;
    __syncwarp();

    float h = gc_b[o] + ax0 * gc_w[o];       // f = 0 row (inputs channel)
    #pragma unroll
    for (int f = 0; f < HH; ++f)
        h += sax[f] * gc_w[(f+1)*HH + o];

    // layernorm over hidden dim (warp of 32)
    float mu = h;
    #pragma unroll
    for (int off = 16; off; off >>= 1) mu += __shfl_xor_sync(0xffffffffu, mu, off);
    mu *= (1.f/HH);
    float dv = h - mu;
    float v = dv*dv;
    #pragma unroll
    for (int off = 16; off; off >>= 1) v += __shfl_xor_sync(0xffffffffu, v, off);
    v *= (1.f/HH);
    float out = dv * rsqrtf(v + 1e-5f) * ln_g[o] + ln_b[o];
    g_hs[(size_t)blk*HH + o] = out;          // == b*3200 + m*32 + o
}

// ===================== stage 1: gating partials (full-chip) =====================
__global__ void k_gates_part() {
    int part = blockIdx.x;           // 0..GPARTS-1
    int b    = blockIdx.y;           // batch
    int tid  = threadIdx.x;          // 256 threads
    __shared__ float sh[DD];
    __shared__ float ct[10], st[10];
    __shared__ float red[3][256];

    if (tid < 10) { ct[tid] = cospif(0.2f * tid); st[tid] = sinpif(0.2f * tid); }
    for (int i = tid; i < DD; i += 256) sh[i] = g_hs[(size_t)b*DD + i];
    __syncthreads();

    float ps = 0.f, ss = 0.f, ns = 0.f;
    for (int w = part + GPARTS*tid; w < NW; w += GPARTS*256) {
        int s0 = 2*w;
        float x[10];
        #pragma unroll
        for (int j = 0; j < 10; ++j) x[j] = sh[s0 + j];
        #pragma unroll
        for (int k = 0; k < 10; ++k) {
            float re = 0.f, im = 0.f;
            #pragma unroll
            for (int j = 0; j < 10; ++j) {
                int t = (j*k) % 10;
                re += x[j] * ct[t];
                im += x[j] * st[t];
            }
            ps += sqrtf(re*re + im*im);
        }
        #pragma unroll
        for (int j = 0; j < 9; ++j) ss += fabsf(x[j+1] - x[j]);
    }
    for (int i = part + GPARTS*tid; i < DD-2; i += GPARTS*256)
        ns += fabsf(sh[i+2] - 2.f*sh[i+1] + sh[i]);

    red[0][tid] = ps; red[1][tid] = ss; red[2][tid] = ns;
    __syncthreads();
    for (int off = 128; off; off >>= 1) {
        if (tid < off) {
            red[0][tid] += red[0][tid+off];
            red[1][tid] += red[1][tid+off];
            red[2][tid] += red[2][tid+off];
        }
        __syncthreads();
    }
    if (tid == 0) {
        g_gpart[b][part][0] = red[0][0];
        g_gpart[b][part][1] = red[1][0];
        g_gpart[b][part][2] = red[2][0];
    }
}

// ===================== stage 2: gates finalize (per-block) + feature tensor ========
__global__ void k_featgates(const float* __restrict__ mnp, const float* __restrict__ mxp,
                            const float* __restrict__ mns, const float* __restrict__ mxs,
                            const float* __restrict__ mnn, const float* __restrict__ mxn) {
    __shared__ float sg[BATCH][3];
    int tid = threadIdx.x;
    if (tid < BATCH) {
        int b = tid;
        float psum = 0.f, ssum = 0.f, nsum = 0.f;
        #pragma unroll
        for (int k = 0; k < GPARTS; ++k) {
            psum += g_gpart[b][k][0];
            ssum += g_gpart[b][k][1];
            nsum += g_gpart[b][k][2];
        }
        float pstat = psum / (float)(NW*10);
        float sstat = ssum / (float)(NW*9);
        float nstat = nsum / (float)(DD-2);
        float p  = fabsf((pstat - *mnp) / (*mxp - *mnp + 1e-8f));
        float s  = 1.f - fabsf((sstat - *mns) / (*mxs - *mns + 1e-8f));
        float nv = fabsf((nstat - *mnn) / (*mxn - *mnn + 1e-8f));
        float a0 = fabsf(p), a1 = fabsf(s), a2 = fabsf(nv);
        float mm = fmaxf(a0, fmaxf(a1, a2));
        float e0 = expf(a0-mm), e1 = expf(a1-mm), e2 = expf(a2-mm);
        float inv = 1.f / (e0 + e1 + e2);
        sg[b][0] = e0*inv; sg[b][1] = e1*inv; sg[b][2] = e2*inv;
    }
    __syncthreads();

    int idx = blockIdx.x*blockDim.x + tid;
    if (idx >= BATCH*DD) return;
    int b = idx & 31;
    int i = idx >> 5;
    float x  = g_hs[(size_t)b*DD + i];
    float g0 = sg[b][0], g1 = sg[b][1], g2 = sg[b][2];
    float* fo = g_feat + (size_t)i*(NF*BATCH) + b;

    // Chebyshev: cos(d*arccos(tanh(xc))) == T_d(tanh(xc)) exactly
    float t  = tanhf(g0*x);
    float t2 = 2.f*t*t - 1.f;
    float t3 = 2.f*t*t2 - t;
    fo[0*BATCH] = 1.f; fo[1*BATCH] = t; fo[2*BATCH] = t2; fo[3*BATCH] = t3;

    // SiLU + B-spline bases (Cox-de Boor, uniform grid, K=3, GRID=5)
    float xb = g1*x;
    fo[4*BATCH] = xb / (1.f + expf(-xb));
    float bb[11];
    #pragma unroll
    for (int tt = 0; tt < 11; ++tt) {
        float gl = (float)(tt-3) * 0.4f - 1.f;
        float gr = (float)(tt-2) * 0.4f - 1.f;
        bb[tt] = (xb >= gl && xb < gr) ? 1.f : 0.f;
    }
    #pragma unroll
    for (int d = 1; d <= 3; ++d) {
        float inv = 1.f / (0.4f * (float)d);
        #pragma unroll
        for (int tt = 0; tt < 10; ++tt) {
            if (tt < 11 - d) {
                float gl = (float)(tt-3) * 0.4f - 1.f;          // grid[tt]
                float gr = (float)(tt+d+1-3) * 0.4f - 1.f;      // grid[tt+d+1]
                bb[tt] = (xb - gl)*inv*bb[tt] + (gr - xb)*inv*bb[tt+1];
            }
        }
    }
    #pragma unroll
    for (int k = 0; k < 8; ++k) fo[(5+k)*BATCH] = bb[k];

    // Taylor powers
    float xt = g2*x;
    fo[13*BATCH] = xt;
    fo[14*BATCH] = xt*xt;
    fo[15*BATCH] = xt*xt*xt;
}

// ===================== stage 3: fused 16-feature contraction (2 outputs/thread) ====
__device__ __forceinline__ void cpa16(void* s, const void* g) {
    unsigned ss = (unsigned)__cvta_generic_to_shared(s);
    asm volatile("cp.async.cg.shared.global [%0], [%1], 16;" :: "r"(ss), "l"(g));
}

__device__ __forceinline__ void loadW16(float* wv, int i, int o, float bwv,
                                        const float* __restrict__ cheb,
                                        const float* __restrict__ spline,
                                        const float* __restrict__ taylor) {
    float4 cw = *(const float4*)(cheb + (size_t)i*(DD*4) + (size_t)o*4);
    wv[0]=cw.x; wv[1]=cw.y; wv[2]=cw.z; wv[3]=cw.w;
    wv[4]=bwv;
    const float4* sp = (const float4*)(spline + (size_t)o*(DD*8) + (size_t)i*8);
    float4 s0 = sp[0], s1 = sp[1];
    wv[5]=s0.x; wv[6]=s0.y; wv[7]=s0.z; wv[8]=s0.w;
    wv[9]=s1.x; wv[10]=s1.y; wv[11]=s1.z; wv[12]=s1.w;
    const float* tp = taylor + (size_t)i*(DD*3) + (size_t)o*3;
    wv[13]=__ldg(tp+0); wv[14]=__ldg(tp+1); wv[15]=__ldg(tp+2);
}

// pack scalar float into both halves of a 64-bit reg with a single MOV
__device__ __forceinline__ unsigned long long dup2(float w) {
    unsigned long long r;
    asm("mov.b64 %0, {%1, %1};" : "=l"(r) : "f"(w));
    return r;
}

__global__ void __launch_bounds__(TO, 8) k_gemm(const float* __restrict__ cheb,
                                                const float* __restrict__ basew,
                                                const float* __restrict__ spline,
                                                const float* __restrict__ taylor) {
    int o0 = blockIdx.x*(2*TO) + threadIdx.x;   // blockIdx.x in [0,25)
    int o1 = o0 + TO;
    int sp = blockIdx.y;
    int i0 = sp * ILEN;

    __shared__ __align__(16) float sf[2][CI*NF*BATCH];  // 2 x 8 KB
    unsigned long long acc0[16], acc1[16];               // packed f32x2 per batch pair
    #pragma unroll
    for (int p = 0; p < 16; ++p) { acc0[p] = 0ull; acc1[p] = 0ull; }

    // prologue: stage chunk 0 (64 threads x 8 float4 = 512 float4 = 8 KB)
    {
        const float4* src = (const float4*)(g_feat + (size_t)i0*(NF*BATCH));
        #pragma unroll
        for (int r = 0; r < 8; ++r)
            cpa16(&((float4*)sf[0])[threadIdx.x + r*TO], &src[threadIdx.x + r*TO]);
        asm volatile("cp.async.commit_group;");
    }

    for (int c = 0; c < NCHUNK; ++c) {
        if (c + 1 < NCHUNK) {
            const float4* src = (const float4*)(g_feat + (size_t)(i0 + (c+1)*CI)*(NF*BATCH));
            float4* dst = (float4*)sf[(c+1)&1];
            #pragma unroll
            for (int r = 0; r < 8; ++r)
                cpa16(&dst[threadIdx.x + r*TO], &src[threadIdx.x + r*TO]);
            asm volatile("cp.async.commit_group;");
            asm volatile("cp.async.wait_group 1;");
        } else {
            asm volatile("cp.async.wait_group 0;");
        }
        __syncthreads();

        const float* sb = sf[c&1];
        int ibase = i0 + c*CI;

        // basew for this chunk (contiguous in i): 1 float4 per o
        float bw0[4], bw1[4];
        {
            float4 a = *(const float4*)(basew + (size_t)o0*DD + ibase);
            bw0[0]=a.x; bw0[1]=a.y; bw0[2]=a.z; bw0[3]=a.w;
            float4 b = *(const float4*)(basew + (size_t)o1*DD + ibase);
            bw1[0]=b.x; bw1[1]=b.y; bw1[2]=b.z; bw1[3]=b.w;
        }

        #pragma unroll
        for (int ii = 0; ii < CI; ++ii) {
            int i = ibase + ii;
            float wv0[16], wv1[16];
            loadW16(wv0, i, o0, bw0[ii], cheb, spline, taylor);
            loadW16(wv1, i, o1, bw1[ii], cheb, spline, taylor);

            #pragma unroll
            for (int f = 0; f < 16; ++f) {
                unsigned long long wA = dup2(wv0[f]);
                unsigned long long wB = dup2(wv1[f]);
                const ulonglong2* fp = (const ulonglong2*)&sb[ii*(NF*BATCH) + f*BATCH];
                #pragma unroll
                for (int p = 0; p < 8; ++p) {
                    ulonglong2 q = fp[p];   // one LDS.128 feeds 4 FFMA2
                    asm("fma.rn.f32x2 %0, %1, %2, %0;" : "+l"(acc0[2*p])   : "l"(q.x), "l"(wA));
                    asm("fma.rn.f32x2 %0, %1, %2, %0;" : "+l"(acc0[2*p+1]) : "l"(q.y), "l"(wA));
                    asm("fma.rn.f32x2 %0, %1, %2, %0;" : "+l"(acc1[2*p])   : "l"(q.x), "l"(wB));
                    asm("fma.rn.f32x2 %0, %1, %2, %0;" : "+l"(acc1[2*p+1]) : "l"(q.y), "l"(wB));
                }
            }
        }
        __syncthreads();
    }

    #pragma unroll
    for (int p = 0; p < 16; ++p) {
        float2 v0 = *(float2*)&acc0[p];
        float2 v1 = *(float2*)&acc1[p];
        g_scratch[((size_t)sp*BATCH + (2*p  ))*DD + o0] = v0.x;
        g_scratch[((size_t)sp*BATCH + (2*p+1))*DD + o0] = v0.y;
        g_scratch[((size_t)sp*BATCH + (2*p  ))*DD + o1] = v1.x;
        g_scratch[((size_t)sp*BATCH + (2*p+1))*DD + o1] = v1.y;
    }
}

// ===================== stage 4: split reduction -> d_out =====================
__global__ void k_reduce(float* __restrict__ out) {
    int j = blockIdx.x*blockDim.x + threadIdx.x;
    if (j < BATCH*DD) {
        float s = 0.f;
        #pragma unroll 10
        for (int k = 0; k < NSPLIT; ++k)
            s += g_scratch[(size_t)k*(BATCH*DD) + j];
        out[j] = s;
    }
}

extern "C" void kernel_launch(void* const* d_in, const int* in_sizes, int n_in,
                              void* d_out, int out_size) {
    const float* inputs = (const float*)d_in[0];
    const float* hidden = (const float*)d_in[1];
    const float* lap    = (const float*)d_in[2];
    const float* corr   = (const float*)d_in[3];
    const float* gc_w   = (const float*)d_in[4];
    const float* gc_b   = (const float*)d_in[5];
    const float* ln_g   = (const float*)d_in[6];
    const float* ln_b   = (const float*)d_in[7];
    const float* cheb   = (const float*)d_in[8];
    const float* basew  = (const float*)d_in[9];
    const float* spline = (const float*)d_in[10];
    const float* taylor = (const float*)d_in[11];

    k_gconv<<<BATCH*NN, 32>>>(inputs, hidden, lap, corr, gc_w, gc_b, ln_g, ln_b);
    k_gates_part<<<dim3(GPARTS, BATCH), 256>>>();
    k_featgates<<<(BATCH*DD + 255)/256, 256>>>((const float*)d_in[12], (const float*)d_in[13],
                                               (const float*)d_in[14], (const float*)d_in[15],
                                               (const float*)d_in[16], (const float*)d_in[17]);
    k_gemm<<<dim3(DD/(2*TO), NSPLIT), TO>>>(cheb, basew, spline, taylor);
    k_reduce<<<(BATCH*DD + 255)/256, 256>>>((float*)d_out);
}

// round 8
// speedup vs baseline: 1.4340x; 1.1424x over previous
#include <cuda_runtime.h>
#include <cstdint>

#define BATCH 32
#define NN 100
#define HH 32
#define DD 3200
#define NF 16
#define NSPLIT 100
#define ILEN (DD/NSPLIT)     // 32
#define CI 4
#define NCHUNK (ILEN/CI)     // 8
#define TO 128               // gemm threads: 64 output-lanes x 2 batch-halves
#define NW 1596              // unfold window count
#define GPARTS 5

// ---- scratch (device globals: allocation-free) ----
__device__ float g_hs[BATCH*DD];
__device__ float g_gpart[BATCH][GPARTS][3];
__device__ float g_feat[(size_t)DD*NF*BATCH];          // [i][f][b]  6.55 MB
__device__ float g_scratch[(size_t)NSPLIT*BATCH*DD];   // 41 MB

// ===================== stage 0: graph conv + layernorm -> hs (alpha fused) ==========
__global__ void k_gconv(const float* __restrict__ inputs,
                        const float* __restrict__ hidden,
                        const float* __restrict__ lap,
                        const float* __restrict__ corr,
                        const float* __restrict__ gc_w,
                        const float* __restrict__ gc_b,
                        const float* __restrict__ ln_g,
                        const float* __restrict__ ln_b) {
    int blk = blockIdx.x;            // b*100 + m
    int b = blk / NN;
    int m = blk % NN;
    int o = threadIdx.x;             // 0..31, one warp

    __shared__ float salpha[NN];
    for (int n = o; n < NN; n += 32) {
        float s = 0.f;
        #pragma unroll 4
        for (int bb = 0; bb < BATCH; ++bb) s += inputs[bb*NN + n];
        s *= (1.f/BATCH);
        salpha[n] = 1.f / (1.f + expf(-s));
    }
    __syncwarp();

    float axh = 0.f, ax0 = 0.f;
    for (int n = 0; n < NN; ++n) {
        float al = salpha[n];
        float a  = al * lap[m*NN + n] + (1.f - al) * corr[m*NN + n];
        ax0 += a * inputs[b*NN + n];
        axh += a * hidden[(size_t)(b*NN + n)*HH + o];
    }
    __shared__ float sax[HH];
    sax[o] = axh;
    __syncwarp();

    float h = gc_b[o] + ax0 * gc_w[o];       // f = 0 row (inputs channel)
    #pragma unroll
    for (int f = 0; f < HH; ++f)
        h += sax[f] * gc_w[(f+1)*HH + o];

    // layernorm over hidden dim (warp of 32)
    float mu = h;
    #pragma unroll
    for (int off = 16; off; off >>= 1) mu += __shfl_xor_sync(0xffffffffu, mu, off);
    mu *= (1.f/HH);
    float dv = h - mu;
    float v = dv*dv;
    #pragma unroll
    for (int off = 16; off; off >>= 1) v += __shfl_xor_sync(0xffffffffu, v, off);
    v *= (1.f/HH);
    float out = dv * rsqrtf(v + 1e-5f) * ln_g[o] + ln_b[o];
    g_hs[(size_t)blk*HH + o] = out;          // == b*3200 + m*32 + o
}

// ===================== stage 1: gating partials (full-chip) =====================
__global__ void k_gates_part() {
    int part = blockIdx.x;           // 0..GPARTS-1
    int b    = blockIdx.y;           // batch
    int tid  = threadIdx.x;          // 256 threads
    __shared__ float sh[DD];
    __shared__ float ct[10], st[10];
    __shared__ float red[3][256];

    if (tid < 10) { ct[tid] = cospif(0.2f * tid); st[tid] = sinpif(0.2f * tid); }
    for (int i = tid; i < DD; i += 256) sh[i] = g_hs[(size_t)b*DD + i];
    __syncthreads();

    float ps = 0.f, ss = 0.f, ns = 0.f;
    for (int w = part + GPARTS*tid; w < NW; w += GPARTS*256) {
        int s0 = 2*w;
        float x[10];
        #pragma unroll
        for (int j = 0; j < 10; ++j) x[j] = sh[s0 + j];
        #pragma unroll
        for (int k = 0; k < 10; ++k) {
            float re = 0.f, im = 0.f;
            #pragma unroll
            for (int j = 0; j < 10; ++j) {
                int t = (j*k) % 10;
                re += x[j] * ct[t];
                im += x[j] * st[t];
            }
            ps += sqrtf(re*re + im*im);
        }
        #pragma unroll
        for (int j = 0; j < 9; ++j) ss += fabsf(x[j+1] - x[j]);
    }
    for (int i = part + GPARTS*tid; i < DD-2; i += GPARTS*256)
        ns += fabsf(sh[i+2] - 2.f*sh[i+1] + sh[i]);

    red[0][tid] = ps; red[1][tid] = ss; red[2][tid] = ns;
    __syncthreads();
    for (int off = 128; off; off >>= 1) {
        if (tid < off) {
            red[0][tid] += red[0][tid+off];
            red[1][tid] += red[1][tid+off];
            red[2][tid] += red[2][tid+off];
        }
        __syncthreads();
    }
    if (tid == 0) {
        g_gpart[b][part][0] = red[0][0];
        g_gpart[b][part][1] = red[1][0];
        g_gpart[b][part][2] = red[2][0];
    }
}

// ===================== stage 2: gates finalize (per-block) + feature tensor ========
__global__ void k_featgates(const float* __restrict__ mnp, const float* __restrict__ mxp,
                            const float* __restrict__ mns, const float* __restrict__ mxs,
                            const float* __restrict__ mnn, const float* __restrict__ mxn) {
    __shared__ float sg[BATCH][3];
    int tid = threadIdx.x;
    if (tid < BATCH) {
        int b = tid;
        float psum = 0.f, ssum = 0.f, nsum = 0.f;
        #pragma unroll
        for (int k = 0; k < GPARTS; ++k) {
            psum += g_gpart[b][k][0];
            ssum += g_gpart[b][k][1];
            nsum += g_gpart[b][k][2];
        }
        float pstat = psum / (float)(NW*10);
        float sstat = ssum / (float)(NW*9);
        float nstat = nsum / (float)(DD-2);
        float p  = fabsf((pstat - *mnp) / (*mxp - *mnp + 1e-8f));
        float s  = 1.f - fabsf((sstat - *mns) / (*mxs - *mns + 1e-8f));
        float nv = fabsf((nstat - *mnn) / (*mxn - *mnn + 1e-8f));
        float a0 = fabsf(p), a1 = fabsf(s), a2 = fabsf(nv);
        float mm = fmaxf(a0, fmaxf(a1, a2));
        float e0 = expf(a0-mm), e1 = expf(a1-mm), e2 = expf(a2-mm);
        float inv = 1.f / (e0 + e1 + e2);
        sg[b][0] = e0*inv; sg[b][1] = e1*inv; sg[b][2] = e2*inv;
    }
    __syncthreads();

    int idx = blockIdx.x*blockDim.x + tid;
    if (idx >= BATCH*DD) return;
    int b = idx & 31;
    int i = idx >> 5;
    float x  = g_hs[(size_t)b*DD + i];
    float g0 = sg[b][0], g1 = sg[b][1], g2 = sg[b][2];
    float* fo = g_feat + (size_t)i*(NF*BATCH) + b;

    // Chebyshev: cos(d*arccos(tanh(xc))) == T_d(tanh(xc)) exactly
    float t  = tanhf(g0*x);
    float t2 = 2.f*t*t - 1.f;
    float t3 = 2.f*t*t2 - t;
    fo[0*BATCH] = 1.f; fo[1*BATCH] = t; fo[2*BATCH] = t2; fo[3*BATCH] = t3;

    // SiLU + B-spline bases (Cox-de Boor, uniform grid, K=3, GRID=5)
    float xb = g1*x;
    fo[4*BATCH] = xb / (1.f + expf(-xb));
    float bb[11];
    #pragma unroll
    for (int tt = 0; tt < 11; ++tt) {
        float gl = (float)(tt-3) * 0.4f - 1.f;
        float gr = (float)(tt-2) * 0.4f - 1.f;
        bb[tt] = (xb >= gl && xb < gr) ? 1.f : 0.f;
    }
    #pragma unroll
    for (int d = 1; d <= 3; ++d) {
        float inv = 1.f / (0.4f * (float)d);
        #pragma unroll
        for (int tt = 0; tt < 10; ++tt) {
            if (tt < 11 - d) {
                float gl = (float)(tt-3) * 0.4f - 1.f;          // grid[tt]
                float gr = (float)(tt+d+1-3) * 0.4f - 1.f;      // grid[tt+d+1]
                bb[tt] = (xb - gl)*inv*bb[tt] + (gr - xb)*inv*bb[tt+1];
            }
        }
    }
    #pragma unroll
    for (int k = 0; k < 8; ++k) fo[(5+k)*BATCH] = bb[k];

    // Taylor powers
    float xt = g2*x;
    fo[13*BATCH] = xt;
    fo[14*BATCH] = xt*xt;
    fo[15*BATCH] = xt*xt*xt;
}

// ===================== stage 3: fused contraction (2 out x 16 batches / thread) ====
__device__ __forceinline__ void cpa16(void* s, const void* g) {
    unsigned ss = (unsigned)__cvta_generic_to_shared(s);
    asm volatile("cp.async.cg.shared.global [%0], [%1], 16;" :: "r"(ss), "l"(g));
}

__device__ __forceinline__ void loadW16(float* wv, int i, int o, float bwv,
                                        const float* __restrict__ cheb,
                                        const float* __restrict__ spline,
                                        const float* __restrict__ taylor) {
    float4 cw = *(const float4*)(cheb + (size_t)i*(DD*4) + (size_t)o*4);
    wv[0]=cw.x; wv[1]=cw.y; wv[2]=cw.z; wv[3]=cw.w;
    wv[4]=bwv;
    const float4* sp = (const float4*)(spline + (size_t)o*(DD*8) + (size_t)i*8);
    float4 s0 = sp[0], s1 = sp[1];
    wv[5]=s0.x; wv[6]=s0.y; wv[7]=s0.z; wv[8]=s0.w;
    wv[9]=s1.x; wv[10]=s1.y; wv[11]=s1.z; wv[12]=s1.w;
    const float* tp = taylor + (size_t)i*(DD*3) + (size_t)o*3;
    wv[13]=__ldg(tp+0); wv[14]=__ldg(tp+1); wv[15]=__ldg(tp+2);
}

// pack scalar float into both halves of a 64-bit reg with a single MOV
__device__ __forceinline__ unsigned long long dup2(float w) {
    unsigned long long r;
    asm("mov.b64 %0, {%1, %1};" : "=l"(r) : "f"(w));
    return r;
}

__global__ void __launch_bounds__(TO, 5) k_gemm(const float* __restrict__ cheb,
                                                const float* __restrict__ basew,
                                                const float* __restrict__ spline,
                                                const float* __restrict__ taylor) {
    int tid = threadIdx.x;
    int bh  = tid & 1;                // batch half: 0 -> b[0:16), 1 -> b[16:32)
    int oo  = tid >> 1;               // 0..63
    int o0  = blockIdx.x*128 + oo;    // blockIdx.x in [0,25)
    int o1  = o0 + 64;
    int sp  = blockIdx.y;
    int i0  = sp * ILEN;

    __shared__ __align__(16) float sf[2][CI*NF*BATCH];  // 2 x 8 KB
    unsigned long long acc0[8], acc1[8];                 // 16 batches (this half) per output
    #pragma unroll
    for (int p = 0; p < 8; ++p) { acc0[p] = 0ull; acc1[p] = 0ull; }

    // prologue: stage chunk 0 (128 threads x 4 float4 = 512 float4 = 8 KB)
    {
        const float4* src = (const float4*)(g_feat + (size_t)i0*(NF*BATCH));
        #pragma unroll
        for (int r = 0; r < 4; ++r)
            cpa16(&((float4*)sf[0])[tid + r*TO], &src[tid + r*TO]);
        asm volatile("cp.async.commit_group;");
    }

    for (int c = 0; c < NCHUNK; ++c) {
        if (c + 1 < NCHUNK) {
            const float4* src = (const float4*)(g_feat + (size_t)(i0 + (c+1)*CI)*(NF*BATCH));
            float4* dst = (float4*)sf[(c+1)&1];
            #pragma unroll
            for (int r = 0; r < 4; ++r)
                cpa16(&dst[tid + r*TO], &src[tid + r*TO]);
            asm volatile("cp.async.commit_group;");
            asm volatile("cp.async.wait_group 1;");
        } else {
            asm volatile("cp.async.wait_group 0;");
        }
        __syncthreads();

        const float* sb = sf[c&1];
        int ibase = i0 + c*CI;

        // basew for this chunk (contiguous in i): 1 float4 per o
        float bw0[4], bw1[4];
        {
            float4 a = *(const float4*)(basew + (size_t)o0*DD + ibase);
            bw0[0]=a.x; bw0[1]=a.y; bw0[2]=a.z; bw0[3]=a.w;
            float4 b = *(const float4*)(basew + (size_t)o1*DD + ibase);
            bw1[0]=b.x; bw1[1]=b.y; bw1[2]=b.z; bw1[3]=b.w;
        }

        #pragma unroll
        for (int ii = 0; ii < CI; ++ii) {
            int i = ibase + ii;
            float wv0[16], wv1[16];
            loadW16(wv0, i, o0, bw0[ii], cheb, spline, taylor);
            loadW16(wv1, i, o1, bw1[ii], cheb, spline, taylor);

            #pragma unroll
            for (int f = 0; f < 16; ++f) {
                unsigned long long wA = dup2(wv0[f]);
                unsigned long long wB = dup2(wv1[f]);
                // this thread's 16-batch half of feature row f
                const ulonglong2* fp = (const ulonglong2*)&sb[ii*(NF*BATCH) + f*BATCH + bh*16];
                #pragma unroll
                for (int p = 0; p < 4; ++p) {
                    ulonglong2 q = fp[p];   // one LDS.128 feeds 4 FFMA2
                    asm("fma.rn.f32x2 %0, %1, %2, %0;" : "+l"(acc0[2*p])   : "l"(q.x), "l"(wA));
                    asm("fma.rn.f32x2 %0, %1, %2, %0;" : "+l"(acc0[2*p+1]) : "l"(q.y), "l"(wA));
                    asm("fma.rn.f32x2 %0, %1, %2, %0;" : "+l"(acc1[2*p])   : "l"(q.x), "l"(wB));
                    asm("fma.rn.f32x2 %0, %1, %2, %0;" : "+l"(acc1[2*p+1]) : "l"(q.y), "l"(wB));
                }
            }
        }
        __syncthreads();
    }

    #pragma unroll
    for (int p = 0; p < 8; ++p) {
        float2 v0 = *(float2*)&acc0[p];
        float2 v1 = *(float2*)&acc1[p];
        int b = bh*16 + 2*p;
        g_scratch[((size_t)sp*BATCH + b    )*DD + o0] = v0.x;
        g_scratch[((size_t)sp*BATCH + b + 1)*DD + o0] = v0.y;
        g_scratch[((size_t)sp*BATCH + b    )*DD + o1] = v1.x;
        g_scratch[((size_t)sp*BATCH + b + 1)*DD + o1] = v1.y;
    }
}

// ===================== stage 4: split reduction -> d_out =====================
__global__ void k_reduce(float* __restrict__ out) {
    int j = blockIdx.x*blockDim.x + threadIdx.x;
    if (j < BATCH*DD) {
        float s = 0.f;
        #pragma unroll 10
        for (int k = 0; k < NSPLIT; ++k)
            s += g_scratch[(size_t)k*(BATCH*DD) + j];
        out[j] = s;
    }
}

extern "C" void kernel_launch(void* const* d_in, const int* in_sizes, int n_in,
                              void* d_out, int out_size) {
    const float* inputs = (const float*)d_in[0];
    const float* hidden = (const float*)d_in[1];
    const float* lap    = (const float*)d_in[2];
    const float* corr   = (const float*)d_in[3];
    const float* gc_w   = (const float*)d_in[4];
    const float* gc_b   = (const float*)d_in[5];
    const float* ln_g   = (const float*)d_in[6];
    const float* ln_b   = (const float*)d_in[7];
    const float* cheb   = (const float*)d_in[8];
    const float* basew  = (const float*)d_in[9];
    const float* spline = (const float*)d_in[10];
    const float* taylor = (const float*)d_in[11];

    k_gconv<<<BATCH*NN, 32>>>(inputs, hidden, lap, corr, gc_w, gc_b, ln_g, ln_b);
    k_gates_part<<<dim3(GPARTS, BATCH), 256>>>();
    k_featgates<<<(BATCH*DD + 255)/256, 256>>>((const float*)d_in[12], (const float*)d_in[13],
                                               (const float*)d_in[14], (const float*)d_in[15],
                                               (const float*)d_in[16], (const float*)d_in[17]);
    k_gemm<<<dim3(DD/128, NSPLIT), TO>>>(cheb, basew, spline, taylor);
    k_reduce<<<(BATCH*DD + 255)/256, 256>>>((float*)d_out);
}